// round 1
// baseline (speedup 1.0000x reference)
#include <cuda_runtime.h>
#include <math.h>

#define INPUT_SIZE 32768
#define FILTER_LEN 8192
#define NUM_CLASSES 512
#define TCLEN 40960      // conv full-length rounded (40959 real outputs, [40959]=0)
#define OUTLEN 65536

// Conv tiling
#define CT_T 1024        // outputs per block
#define CT_KC 512        // filter-chunk per block
#define CT_KCHUNKS 16    // 8192 / 512
#define CT_THREADS 128   // CT_T / 8 outputs per thread

static __device__ float  g_part[CT_KCHUNKS * TCLEN]; // split-K partials (deterministic, no atomics)
static __device__ float  g_tc[TCLEN];                // current layer conv output
static __device__ float  g_x[INPUT_SIZE];            // next-layer conv input
static __device__ float  g_out3[OUTLEN];             // final layer full vector
static __device__ double g_logits[NUM_CLASSES];      // raw trans @ out3
static __device__ double g_acc[16];                  // [3i..3i+2]=Stt,Stb,Sbb ; [12]=||out3||^2

__global__ void k_init() {
    if (threadIdx.x < 16) g_acc[threadIdx.x] = 0.0;
}

// tc[j] = sum_k w[k] * x[j-k], zero-padded x, split by filter chunk (blockIdx.y)
__global__ void __launch_bounds__(CT_THREADS) k_conv(const float* __restrict__ xin,
                                                     const float* __restrict__ w,
                                                     int layer) {
    const float* x = (layer == 0) ? xin : g_x;
    __shared__ float sw[CT_KC];
    __shared__ float sx[CT_T + CT_KC];  // 1536 (need 1535)

    const int jBase  = blockIdx.x * CT_T;
    const int k0     = blockIdx.y * CT_KC;
    const int lowIdx = jBase - k0 - (CT_KC - 1);

    for (int t = threadIdx.x; t < CT_KC; t += CT_THREADS)
        sw[t] = w[k0 + t];
    for (int t = threadIdx.x; t < CT_T + CT_KC - 1; t += CT_THREADS) {
        int gi = lowIdx + t;
        sx[t] = (gi >= 0 && gi < INPUT_SIZE) ? x[gi] : 0.0f;
    }
    __syncthreads();

    float acc[8];
#pragma unroll
    for (int r = 0; r < 8; r++) acc[r] = 0.0f;

    // sliding register window: xw[i] = x[j0 - kk - 7 + i], i in [0,15)
    int off = threadIdx.x * 8 + (CT_KC - 8);
    float xw[15];
#pragma unroll
    for (int i = 0; i < 15; i++) xw[i] = sx[off + i];

    for (int kb = 0; kb < CT_KC; kb += 8) {
#pragma unroll
        for (int u = 0; u < 8; u++) {
            float wv = sw[kb + u];
#pragma unroll
            for (int r = 0; r < 8; r++)
                acc[r] = fmaf(wv, xw[r - u + 7], acc[r]);
        }
        if (kb + 8 < CT_KC) {
#pragma unroll
            for (int i = 14; i >= 8; i--) xw[i] = xw[i - 8];
            off -= 8;
#pragma unroll
            for (int i = 0; i < 8; i++) xw[i] = sx[off + i];
        }
    }

    const int j0 = jBase + threadIdx.x * 8;
    float* dst = &g_part[blockIdx.y * TCLEN + j0];
#pragma unroll
    for (int r = 0; r < 8; r++) dst[r] = acc[r];
}

// combine split-K partials -> g_tc ; accumulate Stt, Stb, Sbb (double)
__global__ void k_reduce(const float* __restrict__ bk, int convLen, int slot) {
    __shared__ double sh[256];
    double stt = 0.0, stb = 0.0, sbb = 0.0;
    const int stride = gridDim.x * blockDim.x;
    for (int j = blockIdx.x * blockDim.x + threadIdx.x; j < convLen; j += stride) {
        double bkv = (double)bk[j];
        sbb += bkv * bkv;
        if (j < TCLEN) {
            float tc = 0.0f;
#pragma unroll
            for (int c = 0; c < CT_KCHUNKS; c++) tc += g_part[c * TCLEN + j];
            g_tc[j] = tc;
            double td = (double)tc;
            stt += td * td;
            stb += td * bkv;
        }
    }
    const int t = threadIdx.x;
    sh[t] = stt; __syncthreads();
    for (int s = 128; s > 0; s >>= 1) { if (t < s) sh[t] += sh[t + s]; __syncthreads(); }
    if (t == 0) atomicAdd(&g_acc[slot * 3 + 0], sh[0]);
    __syncthreads();
    sh[t] = stb; __syncthreads();
    for (int s = 128; s > 0; s >>= 1) { if (t < s) sh[t] += sh[t + s]; __syncthreads(); }
    if (t == 0) atomicAdd(&g_acc[slot * 3 + 1], sh[0]);
    __syncthreads();
    sh[t] = sbb; __syncthreads();
    for (int s = 128; s > 0; s >>= 1) { if (t < s) sh[t] += sh[t + s]; __syncthreads(); }
    if (t == 0) atomicAdd(&g_acc[slot * 3 + 2], sh[0]);
}

// scalar coefficients for out = relu((A*g*tc + B*bk)/den) = relu(ca*tc + cb*bk)
static __device__ __forceinline__ void compute_coeffs(int slot, double* pca, double* pcb) {
    const double C  = 1e-5;
    const double SC = sqrt(C);
    double Stt = g_acc[slot * 3 + 0];
    double Stb = g_acc[slot * 3 + 1];
    double Sbb = g_acc[slot * 3 + 2];

    double un = sqrt(Stt); if (un < 1e-15) un = 1e-15;
    double scn = SC * un;
    double gexp = tanh(scn) / scn;           // expmap0 scale
    double nafter = gexp * un;
    double maxnorm = (1.0 - 4e-3) / SC;
    double g = (nafter > maxnorm) ? (maxnorm / un) : gexp;  // proj

    double x2 = g * g * Stt;
    double xy = g * Stb;
    double y2 = Sbb;
    double A  = 1.0 + 2.0 * C * xy + C * y2;
    double B  = 1.0 - C * x2;
    double den = 1.0 + 2.0 * C * xy + C * C * x2 * y2;
    if (den < 1e-15) den = 1e-15;
    *pca = A * g / den;
    *pcb = B / den;
}

// layers 0..2: produce next conv input (first 32768 only; tails are never consumed)
__global__ void k_elem(const float* __restrict__ bk, int slot) {
    __shared__ float s_ca, s_cb;
    if (threadIdx.x == 0) {
        double ca, cb;
        compute_coeffs(slot, &ca, &cb);
        s_ca = (float)ca; s_cb = (float)cb;
    }
    __syncthreads();
    const float ca = s_ca, cb = s_cb;
    int j = blockIdx.x * blockDim.x + threadIdx.x;
    if (j < INPUT_SIZE)
        g_x[j] = fmaxf(0.0f, ca * g_tc[j] + cb * bk[j]);
}

// layer 3: full 65536 output + ||out3||^2
__global__ void k_elem3(const float* __restrict__ bk) {
    __shared__ float s_ca, s_cb;
    __shared__ double sh[256];
    if (threadIdx.x == 0) {
        double ca, cb;
        compute_coeffs(3, &ca, &cb);
        s_ca = (float)ca; s_cb = (float)cb;
    }
    __syncthreads();
    const float ca = s_ca, cb = s_cb;
    int j = blockIdx.x * blockDim.x + threadIdx.x;
    float tcv = (j < TCLEN) ? g_tc[j] : 0.0f;
    float v = fmaxf(0.0f, ca * tcv + cb * bk[j]);
    g_out3[j] = v;
    sh[threadIdx.x] = (double)v * (double)v;
    __syncthreads();
    for (int s = 128; s > 0; s >>= 1) {
        if (threadIdx.x < s) sh[threadIdx.x] += sh[threadIdx.x + s];
        __syncthreads();
    }
    if (threadIdx.x == 0) atomicAdd(&g_acc[12], sh[0]);
}

// logits_raw[r] = trans[r,:] . out3   (logmap0 scale folded in later)
__global__ void __launch_bounds__(256) k_matvec(const float* __restrict__ trans) {
    __shared__ double sh[256];
    const int row = blockIdx.x;
    const float4* tr = (const float4*)(trans + (size_t)row * OUTLEN);
    const float4* ov = (const float4*)g_out3;
    double acc = 0.0;
    for (int i = threadIdx.x; i < OUTLEN / 4; i += 256) {
        float4 a = tr[i];
        float4 b = ov[i];
        acc += (double)a.x * (double)b.x + (double)a.y * (double)b.y
             + (double)a.z * (double)b.z + (double)a.w * (double)b.w;
    }
    sh[threadIdx.x] = acc; __syncthreads();
    for (int s = 128; s > 0; s >>= 1) {
        if (threadIdx.x < s) sh[threadIdx.x] += sh[threadIdx.x + s];
        __syncthreads();
    }
    if (threadIdx.x == 0) g_logits[row] = sh[0];
}

// logmap0 scale, per-row euc_to_hyp (scalar), softmax over 512
__global__ void k_final(float* __restrict__ out) {
    const int t = threadIdx.x;
    const double C  = 1e-5;
    const double SC = sqrt(C);

    double pn = sqrt(g_acc[12]); if (pn < 1e-15) pn = 1e-15;
    double z = SC * pn;
    if (z > 1.0 - 1e-7) z = 1.0 - 1e-7;   // pn >= 0 -> lower clip irrelevant
    double slog = atanh(z) / (SC * pn);

    double l = slog * g_logits[t];
    double un = fabs(l); if (un < 1e-15) un = 1e-15;
    double scn = SC * un;
    double val = tanh(scn) / scn * l;
    double maxnorm = (1.0 - 4e-3) / SC;
    double av = fabs(val); if (av < 1e-15) av = 1e-15;
    if (av > maxnorm) val = val / av * maxnorm;

    __shared__ double sh[NUM_CLASSES];
    sh[t] = val; __syncthreads();
    for (int s = 256; s > 0; s >>= 1) {
        if (t < s) sh[t] = fmax(sh[t], sh[t + s]);
        __syncthreads();
    }
    double m = sh[0];
    __syncthreads();
    double e = exp(val - m);
    sh[t] = e; __syncthreads();
    for (int s = 256; s > 0; s >>= 1) {
        if (t < s) sh[t] += sh[t + s];
        __syncthreads();
    }
    out[t] = (float)(e / sh[0]);
}

extern "C" void kernel_launch(void* const* d_in, const int* in_sizes, int n_in,
                              void* d_out, int out_size) {
    const float* hk = nullptr;
    const float* w[4]  = {nullptr, nullptr, nullptr, nullptr};
    const float* bkk[4] = {nullptr, nullptr, nullptr, nullptr};
    const float* trans = nullptr;
    int wi = 0;
    for (int i = 0; i < n_in; i++) {
        int s = in_sizes[i];
        const float* p = (const float*)d_in[i];
        if      (s == INPUT_SIZE) hk = p;
        else if (s == FILTER_LEN) { if (wi < 4) w[wi++] = p; }
        else if (s == 40960) bkk[0] = p;
        else if (s == 49152) bkk[1] = p;
        else if (s == 57344) bkk[2] = p;
        else if (s == 65536) bkk[3] = p;
        else if (s == NUM_CLASSES * OUTLEN) trans = p;
    }

    const int convLens[4] = {40960, 49152, 57344, 65536};

    k_init<<<1, 32>>>();
    for (int i = 0; i < 4; i++) {
        k_conv<<<dim3(TCLEN / CT_T, CT_KCHUNKS), CT_THREADS>>>(hk, w[i], i);
        k_reduce<<<128, 256>>>(bkk[i], convLens[i], i);
        if (i < 3) k_elem<<<128, 256>>>(bkk[i], i);
        else       k_elem3<<<OUTLEN / 256, 256>>>(bkk[3]);
    }
    k_matvec<<<NUM_CLASSES, 256>>>(trans);
    k_final<<<1, NUM_CLASSES>>>((float*)d_out);
}

// round 2
// speedup vs baseline: 1.0575x; 1.0575x over previous
#include <cuda_runtime.h>
#include <math.h>

#define INPUT_SIZE 32768
#define FILTER_LEN 8192
#define NUM_CLASSES 512
#define TCLEN 40960      // conv full-length rounded (40959 real outputs, [40959]=0)
#define OUTLEN 65536

// Conv tiling
#define CT_T 1024        // outputs per block
#define CT_KC 512        // filter-chunk per block
#define CT_KCHUNKS 16    // 8192 / 512
#define CT_THREADS 128   // CT_T / 8 outputs per thread

static __device__ __align__(16) float g_part[CT_KCHUNKS * TCLEN]; // split-K partials
static __device__ __align__(16) float g_tc[TCLEN];                // current layer conv output
static __device__ __align__(16) float g_out3[OUTLEN];             // final layer full vector
static __device__ double g_logits[NUM_CLASSES];
static __device__ double g_acc[16];      // [3i..3i+2]=Stt,Stb,Sbb ; [12]=||out3||^2
static __device__ float  g_ca[4], g_cb[4];   // per-layer mobius coefficients
static __device__ unsigned g_ctr[4];         // reduce completion tickets

__global__ void k_init() {
    int t = threadIdx.x;
    if (t < 16) g_acc[t] = 0.0;
    if (t < 4)  g_ctr[t] = 0u;
}

// tc[j] = sum_k w[k] * x[j-k]; x for layer>0 is generated inline:
// x[gi] = relu(ca*g_tc[gi] + cb*bkprev[gi])
__global__ void __launch_bounds__(CT_THREADS) k_conv(const float* __restrict__ xin,
                                                     const float* __restrict__ w,
                                                     const float* __restrict__ bkprev,
                                                     int layer) {
    __shared__ __align__(16) float sw[CT_KC];
    __shared__ __align__(16) float sx[CT_T + CT_KC];  // 1536 (need 1535)

    const int tid    = threadIdx.x;
    const int jBase  = blockIdx.x * CT_T;
    const int k0     = blockIdx.y * CT_KC;
    const int lowIdx = jBase - k0 - (CT_KC - 1);

    for (int t = tid; t < CT_KC; t += CT_THREADS)
        sw[t] = w[k0 + t];

    if (layer == 0) {
        for (int t = tid; t < CT_T + CT_KC; t += CT_THREADS) {
            int gi = lowIdx + t;
            sx[t] = (gi >= 0 && gi < INPUT_SIZE) ? xin[gi] : 0.0f;
        }
    } else {
        const float ca = g_ca[layer - 1], cb = g_cb[layer - 1];
        for (int t = tid; t < CT_T + CT_KC; t += CT_THREADS) {
            int gi = lowIdx + t;
            float v = 0.0f;
            if (gi >= 0 && gi < INPUT_SIZE)
                v = fmaxf(0.0f, ca * g_tc[gi] + cb * bkprev[gi]);
            sx[t] = v;
        }
    }
    __syncthreads();

    float acc[8];
#pragma unroll
    for (int r = 0; r < 8; r++) acc[r] = 0.0f;

    // register window xw[i] = sx[b+i], b = tid*8 + 504 - kb (float4-aligned)
    int b = tid * 8 + (CT_KC - 8);
    float xw[16];
#pragma unroll
    for (int i = 0; i < 4; i++) {
        float4 v = *(const float4*)&sx[b + 4 * i];
        xw[4*i+0] = v.x; xw[4*i+1] = v.y; xw[4*i+2] = v.z; xw[4*i+3] = v.w;
    }

    for (int kb = 0; kb < CT_KC; kb += 8) {
        float4 w0 = *(const float4*)&sw[kb];
        float4 w1 = *(const float4*)&sw[kb + 4];
        float wv[8] = {w0.x, w0.y, w0.z, w0.w, w1.x, w1.y, w1.z, w1.w};
#pragma unroll
        for (int u = 0; u < 8; u++) {
#pragma unroll
            for (int r = 0; r < 8; r++)
                acc[r] = fmaf(wv[u], xw[r - u + 7], acc[r]);
        }
        if (kb + 8 < CT_KC) {
#pragma unroll
            for (int i = 15; i >= 8; i--) xw[i] = xw[i - 8];
            b -= 8;
            float4 n0 = *(const float4*)&sx[b];
            float4 n1 = *(const float4*)&sx[b + 4];
            xw[0] = n0.x; xw[1] = n0.y; xw[2] = n0.z; xw[3] = n0.w;
            xw[4] = n1.x; xw[5] = n1.y; xw[6] = n1.z; xw[7] = n1.w;
        }
    }

    float4* dst = (float4*)&g_part[blockIdx.y * TCLEN + jBase + tid * 8];
    dst[0] = make_float4(acc[0], acc[1], acc[2], acc[3]);
    dst[1] = make_float4(acc[4], acc[5], acc[6], acc[7]);
}

// scalar coefficients: out = relu(ca*tc + cb*bk)
static __device__ __forceinline__ void compute_coeffs(int slot, float* pca, float* pcb) {
    const double C  = 1e-5;
    const double SC = sqrt(C);
    double Stt = g_acc[slot * 3 + 0];
    double Stb = g_acc[slot * 3 + 1];
    double Sbb = g_acc[slot * 3 + 2];

    double un = sqrt(Stt); if (un < 1e-15) un = 1e-15;
    double scn = SC * un;
    double gexp = tanh(scn) / scn;            // expmap0 scale
    double nafter = gexp * un;
    double maxnorm = (1.0 - 4e-3) / SC;
    double g = (nafter > maxnorm) ? (maxnorm / un) : gexp;  // proj

    double x2 = g * g * Stt;
    double xy = g * Stb;
    double y2 = Sbb;
    double A  = 1.0 + 2.0 * C * xy + C * y2;
    double B  = 1.0 - C * x2;
    double den = 1.0 + 2.0 * C * xy + C * C * x2 * y2;
    if (den < 1e-15) den = 1e-15;
    *pca = (float)(A * g / den);
    *pcb = (float)(B / den);
}

// combine split-K partials -> g_tc ; accumulate Stt, Stb, Sbb; last block computes coeffs
__global__ void __launch_bounds__(256) k_reduce(const float* __restrict__ bk,
                                                int convLen, int slot) {
    __shared__ double sh[256];
    double stt = 0.0, stb = 0.0, sbb = 0.0;
    const int stride = gridDim.x * blockDim.x;
    for (int j = blockIdx.x * blockDim.x + threadIdx.x; j < convLen; j += stride) {
        double bkv = (double)bk[j];
        sbb += bkv * bkv;
        if (j < TCLEN) {
            float tc = 0.0f;
#pragma unroll
            for (int c = 0; c < CT_KCHUNKS; c++) tc += g_part[c * TCLEN + j];
            g_tc[j] = tc;
            double td = (double)tc;
            stt += td * td;
            stb += td * bkv;
        }
    }
    const int t = threadIdx.x;
    sh[t] = stt; __syncthreads();
    for (int s = 128; s > 0; s >>= 1) { if (t < s) sh[t] += sh[t + s]; __syncthreads(); }
    if (t == 0) atomicAdd(&g_acc[slot * 3 + 0], sh[0]);
    __syncthreads();
    sh[t] = stb; __syncthreads();
    for (int s = 128; s > 0; s >>= 1) { if (t < s) sh[t] += sh[t + s]; __syncthreads(); }
    if (t == 0) atomicAdd(&g_acc[slot * 3 + 1], sh[0]);
    __syncthreads();
    sh[t] = sbb; __syncthreads();
    for (int s = 128; s > 0; s >>= 1) { if (t < s) sh[t] += sh[t + s]; __syncthreads(); }
    if (t == 0) {
        atomicAdd(&g_acc[slot * 3 + 2], sh[0]);
        __threadfence();
        if (atomicAdd(&g_ctr[slot], 1u) == gridDim.x - 1) {
            // all blocks' sums are visible; compute coefficients once
            float ca, cb;
            compute_coeffs(slot, &ca, &cb);
            g_ca[slot] = ca;
            g_cb[slot] = cb;
        }
    }
}

// layer 3: full 65536 output + ||out3||^2
__global__ void __launch_bounds__(256) k_elem3(const float* __restrict__ bk) {
    __shared__ double sh[256];
    const float ca = g_ca[3], cb = g_cb[3];
    int j = blockIdx.x * blockDim.x + threadIdx.x;
    float tcv = (j < TCLEN) ? g_tc[j] : 0.0f;
    float v = fmaxf(0.0f, ca * tcv + cb * bk[j]);
    g_out3[j] = v;
    sh[threadIdx.x] = (double)v * (double)v;
    __syncthreads();
    for (int s = 128; s > 0; s >>= 1) {
        if (threadIdx.x < s) sh[threadIdx.x] += sh[threadIdx.x + s];
        __syncthreads();
    }
    if (threadIdx.x == 0) atomicAdd(&g_acc[12], sh[0]);
}

// logits_raw[r] = trans[r,:] . out3 (8 independent accumulators for ILP)
__global__ void __launch_bounds__(256) k_matvec(const float* __restrict__ trans) {
    __shared__ double sh[256];
    const int row = blockIdx.x;
    const float4* tr = (const float4*)(trans + (size_t)row * OUTLEN);
    const float4* ov = (const float4*)g_out3;
    double acc[8];
#pragma unroll
    for (int i = 0; i < 8; i++) acc[i] = 0.0;
    for (int i = threadIdx.x; i < OUTLEN / 8; i += 256) {
        float4 t0 = tr[2 * i], t1 = tr[2 * i + 1];
        float4 o0 = ov[2 * i], o1 = ov[2 * i + 1];
        acc[0] += (double)t0.x * (double)o0.x;
        acc[1] += (double)t0.y * (double)o0.y;
        acc[2] += (double)t0.z * (double)o0.z;
        acc[3] += (double)t0.w * (double)o0.w;
        acc[4] += (double)t1.x * (double)o1.x;
        acc[5] += (double)t1.y * (double)o1.y;
        acc[6] += (double)t1.z * (double)o1.z;
        acc[7] += (double)t1.w * (double)o1.w;
    }
    double a = ((acc[0] + acc[1]) + (acc[2] + acc[3]))
             + ((acc[4] + acc[5]) + (acc[6] + acc[7]));
    sh[threadIdx.x] = a; __syncthreads();
    for (int s = 128; s > 0; s >>= 1) {
        if (threadIdx.x < s) sh[threadIdx.x] += sh[threadIdx.x + s];
        __syncthreads();
    }
    if (threadIdx.x == 0) g_logits[row] = sh[0];
}

// logmap0 scale, per-row euc_to_hyp (scalar), softmax over 512
__global__ void k_final(float* __restrict__ out) {
    const int t = threadIdx.x;
    const double C  = 1e-5;
    const double SC = sqrt(C);

    double pn = sqrt(g_acc[12]); if (pn < 1e-15) pn = 1e-15;
    double z = SC * pn;
    if (z > 1.0 - 1e-7) z = 1.0 - 1e-7;
    double slog = atanh(z) / (SC * pn);

    double l = slog * g_logits[t];
    double un = fabs(l); if (un < 1e-15) un = 1e-15;
    double scn = SC * un;
    double val = tanh(scn) / scn * l;
    double maxnorm = (1.0 - 4e-3) / SC;
    double av = fabs(val); if (av < 1e-15) av = 1e-15;
    if (av > maxnorm) val = val / av * maxnorm;

    __shared__ double sh[NUM_CLASSES];
    sh[t] = val; __syncthreads();
    for (int s = 256; s > 0; s >>= 1) {
        if (t < s) sh[t] = fmax(sh[t], sh[t + s]);
        __syncthreads();
    }
    double m = sh[0];
    __syncthreads();
    double e = exp(val - m);
    sh[t] = e; __syncthreads();
    for (int s = 256; s > 0; s >>= 1) {
        if (t < s) sh[t] += sh[t + s];
        __syncthreads();
    }
    out[t] = (float)(e / sh[0]);
}

extern "C" void kernel_launch(void* const* d_in, const int* in_sizes, int n_in,
                              void* d_out, int out_size) {
    const float* hk = nullptr;
    const float* w[4]   = {nullptr, nullptr, nullptr, nullptr};
    const float* bkk[4] = {nullptr, nullptr, nullptr, nullptr};
    const float* trans = nullptr;
    int wi = 0;
    for (int i = 0; i < n_in; i++) {
        int s = in_sizes[i];
        const float* p = (const float*)d_in[i];
        if      (s == INPUT_SIZE) hk = p;
        else if (s == FILTER_LEN) { if (wi < 4) w[wi++] = p; }
        else if (s == 40960) bkk[0] = p;
        else if (s == 49152) bkk[1] = p;
        else if (s == 57344) bkk[2] = p;
        else if (s == 65536) bkk[3] = p;
        else if (s == NUM_CLASSES * OUTLEN) trans = p;
    }

    const int convLens[4] = {40960, 49152, 57344, 65536};

    k_init<<<1, 32>>>();
    for (int i = 0; i < 4; i++) {
        const float* bkprev = (i == 0) ? nullptr : bkk[i - 1];
        k_conv<<<dim3(TCLEN / CT_T, CT_KCHUNKS), CT_THREADS>>>(hk, w[i], bkprev, i);
        k_reduce<<<128, 256>>>(bkk[i], convLens[i], i);
    }
    k_elem3<<<OUTLEN / 256, 256>>>(bkk[3]);
    k_matvec<<<NUM_CLASSES, 256>>>(trans);
    k_final<<<1, NUM_CLASSES>>>((float*)d_out);
}

// round 3
// speedup vs baseline: 2.0896x; 1.9759x over previous
#include <cuda_runtime.h>
#include <math.h>

#define INPUT_SIZE 32768
#define FILTER_LEN 8192
#define NUM_CLASSES 512
#define TCLEN 40960      // conv full-length rounded (40959 real outputs, [40959]=0)
#define OUTLEN 65536

// Conv tiling
#define CT_T 1024        // outputs per block
#define CT_KC 512        // filter-chunk per block
#define CT_KCHUNKS 16    // 8192 / 512
#define CT_THREADS 128   // CT_T / 8 outputs per thread

typedef unsigned long long u64;

static __device__ __align__(16) float g_part[CT_KCHUNKS * TCLEN]; // split-K partials
static __device__ __align__(16) float g_tc[TCLEN];                // current layer conv output
static __device__ __align__(16) float g_out3[OUTLEN];             // final layer full vector
static __device__ float  g_logits[NUM_CLASSES];
static __device__ double g_acc[16];      // [3i..3i+2]=Stt,Stb,Sbb ; [12]=||out3||^2
static __device__ float  g_ca[4], g_cb[4];   // per-layer mobius coefficients
static __device__ unsigned g_ctr[4];         // reduce completion tickets

// ---- packed f32x2 helpers (Blackwell) ----
static __device__ __forceinline__ u64 pk2(float lo, float hi) {
    u64 r;
    asm("mov.b64 %0, {%1, %2};" : "=l"(r) : "f"(lo), "f"(hi));
    return r;
}
static __device__ __forceinline__ void fma2(u64& d, u64 a, u64 b) {
    asm("fma.rn.f32x2 %0, %1, %2, %0;" : "+l"(d) : "l"(a), "l"(b));
}
static __device__ __forceinline__ float hsum2(u64 v) {
    float lo, hi;
    asm("mov.b64 {%0, %1}, %2;" : "=f"(lo), "=f"(hi) : "l"(v));
    return lo + hi;
}

__global__ void k_init() {
    int t = threadIdx.x;
    if (t < 16) g_acc[t] = 0.0;
    if (t < 4)  g_ctr[t] = 0u;
}

// tc[j] = sum_k w[k] * x[j-k]; x for layer>0 generated inline:
// x[gi] = relu(ca*g_tc[gi] + cb*bkprev[gi])
// Filter stored REVERSED in smem so x-window ascends with tap index m:
//   acc[r] = sum_m swrev[m] * sx[tid*8 + m + r],  swrev[m] = w[k0 + 511 - m]
__global__ void __launch_bounds__(CT_THREADS) k_conv(const float* __restrict__ xin,
                                                     const float* __restrict__ w,
                                                     const float* __restrict__ bkprev,
                                                     int layer) {
    __shared__ __align__(16) float sw[CT_KC];              // reversed filter chunk
    __shared__ __align__(16) float sx[CT_T + CT_KC];       // 1536 floats

    const int tid    = threadIdx.x;
    const int jBase  = blockIdx.x * CT_T;
    const int k0     = blockIdx.y * CT_KC;
    const int lowIdx = jBase - k0 - (CT_KC - 1);

    for (int t = tid; t < CT_KC; t += CT_THREADS)
        sw[CT_KC - 1 - t] = w[k0 + t];

    if (layer == 0) {
        for (int t = tid; t < CT_T + CT_KC; t += CT_THREADS) {
            int gi = lowIdx + t;
            sx[t] = (gi >= 0 && gi < INPUT_SIZE) ? xin[gi] : 0.0f;
        }
    } else {
        const float ca = g_ca[layer - 1], cb = g_cb[layer - 1];
        for (int t = tid; t < CT_T + CT_KC; t += CT_THREADS) {
            int gi = lowIdx + t;
            float v = 0.0f;
            if (gi >= 0 && gi < INPUT_SIZE)
                v = fmaxf(0.0f, ca * g_tc[gi] + cb * bkprev[gi]);
            sx[t] = v;
        }
    }
    __syncthreads();

    u64 pacc[8];
#pragma unroll
    for (int r = 0; r < 8; r++) pacc[r] = pk2(0.0f, 0.0f);

    const int tb = tid * 8;

    // init window packs xp[i] = (sx[tb+i], sx[tb+i+1]), i = 0..14; last = sx[tb+15]
    u64 xp[15];
    float last;
    {
        float4 a0 = *(const float4*)&sx[tb + 0];
        float4 a1 = *(const float4*)&sx[tb + 4];
        float4 a2 = *(const float4*)&sx[tb + 8];
        float4 a3 = *(const float4*)&sx[tb + 12];
        float f[16] = {a0.x,a0.y,a0.z,a0.w, a1.x,a1.y,a1.z,a1.w,
                       a2.x,a2.y,a2.z,a2.w, a3.x,a3.y,a3.z,a3.w};
#pragma unroll
        for (int i = 0; i < 15; i++) xp[i] = pk2(f[i], f[i + 1]);
        last = f[15];
    }

    for (int kb = 0; kb < CT_KC; kb += 8) {
        float4 w0 = *(const float4*)&sw[kb];
        float4 w1 = *(const float4*)&sw[kb + 4];
        u64 wp0 = pk2(w0.x, w0.y);
        u64 wp1 = pk2(w0.z, w0.w);
        u64 wp2 = pk2(w1.x, w1.y);
        u64 wp3 = pk2(w1.z, w1.w);
#pragma unroll
        for (int r = 0; r < 8; r++) fma2(pacc[r], wp0, xp[r + 0]);
#pragma unroll
        for (int r = 0; r < 8; r++) fma2(pacc[r], wp1, xp[r + 2]);
#pragma unroll
        for (int r = 0; r < 8; r++) fma2(pacc[r], wp2, xp[r + 4]);
#pragma unroll
        for (int r = 0; r < 8; r++) fma2(pacc[r], wp3, xp[r + 6]);

        if (kb + 8 < CT_KC) {
#pragma unroll
            for (int i = 0; i < 7; i++) xp[i] = xp[i + 8];
            float4 n0 = *(const float4*)&sx[tb + kb + 16];
            float4 n1 = *(const float4*)&sx[tb + kb + 20];
            xp[7]  = pk2(last,  n0.x);
            xp[8]  = pk2(n0.x, n0.y);
            xp[9]  = pk2(n0.y, n0.z);
            xp[10] = pk2(n0.z, n0.w);
            xp[11] = pk2(n0.w, n1.x);
            xp[12] = pk2(n1.x, n1.y);
            xp[13] = pk2(n1.y, n1.z);
            xp[14] = pk2(n1.z, n1.w);
            last = n1.w;
        }
    }

    float acc[8];
#pragma unroll
    for (int r = 0; r < 8; r++) acc[r] = hsum2(pacc[r]);

    float4* dst = (float4*)&g_part[blockIdx.y * TCLEN + jBase + tb];
    dst[0] = make_float4(acc[0], acc[1], acc[2], acc[3]);
    dst[1] = make_float4(acc[4], acc[5], acc[6], acc[7]);
}

// scalar coefficients: out = relu(ca*tc + cb*bk)
static __device__ __forceinline__ void compute_coeffs(int slot, float* pca, float* pcb) {
    const double C  = 1e-5;
    const double SC = sqrt(C);
    double Stt = g_acc[slot * 3 + 0];
    double Stb = g_acc[slot * 3 + 1];
    double Sbb = g_acc[slot * 3 + 2];

    double un = sqrt(Stt); if (un < 1e-15) un = 1e-15;
    double scn = SC * un;
    double gexp = tanh(scn) / scn;            // expmap0 scale
    double nafter = gexp * un;
    double maxnorm = (1.0 - 4e-3) / SC;
    double g = (nafter > maxnorm) ? (maxnorm / un) : gexp;  // proj

    double x2 = g * g * Stt;
    double xy = g * Stb;
    double y2 = Sbb;
    double A  = 1.0 + 2.0 * C * xy + C * y2;
    double B  = 1.0 - C * x2;
    double den = 1.0 + 2.0 * C * xy + C * C * x2 * y2;
    if (den < 1e-15) den = 1e-15;
    *pca = (float)(A * g / den);
    *pcb = (float)(B / den);
}

// combine split-K partials -> g_tc ; accumulate Stt, Stb, Sbb; last block computes coeffs
__global__ void __launch_bounds__(256) k_reduce(const float* __restrict__ bk,
                                                int convLen, int slot) {
    __shared__ double sh[256];
    float stt = 0.0f, stb = 0.0f, sbb = 0.0f;
    const int stride = gridDim.x * blockDim.x;
    for (int j = blockIdx.x * blockDim.x + threadIdx.x; j < convLen; j += stride) {
        float bkv = bk[j];
        sbb = fmaf(bkv, bkv, sbb);
        if (j < TCLEN) {
            float tc = 0.0f;
#pragma unroll
            for (int c = 0; c < CT_KCHUNKS; c++) tc += g_part[c * TCLEN + j];
            g_tc[j] = tc;
            stt = fmaf(tc, tc, stt);
            stb = fmaf(tc, bkv, stb);
        }
    }
    const int t = threadIdx.x;
    sh[t] = (double)stt; __syncthreads();
    for (int s = 128; s > 0; s >>= 1) { if (t < s) sh[t] += sh[t + s]; __syncthreads(); }
    if (t == 0) atomicAdd(&g_acc[slot * 3 + 0], sh[0]);
    __syncthreads();
    sh[t] = (double)stb; __syncthreads();
    for (int s = 128; s > 0; s >>= 1) { if (t < s) sh[t] += sh[t + s]; __syncthreads(); }
    if (t == 0) atomicAdd(&g_acc[slot * 3 + 1], sh[0]);
    __syncthreads();
    sh[t] = (double)sbb; __syncthreads();
    for (int s = 128; s > 0; s >>= 1) { if (t < s) sh[t] += sh[t + s]; __syncthreads(); }
    if (t == 0) {
        atomicAdd(&g_acc[slot * 3 + 2], sh[0]);
        __threadfence();
        if (atomicAdd(&g_ctr[slot], 1u) == gridDim.x - 1) {
            float ca, cb;
            compute_coeffs(slot, &ca, &cb);
            g_ca[slot] = ca;
            g_cb[slot] = cb;
        }
    }
}

// layer 3: full 65536 output + ||out3||^2
__global__ void __launch_bounds__(256) k_elem3(const float* __restrict__ bk) {
    __shared__ double sh[256];
    const float ca = g_ca[3], cb = g_cb[3];
    int j = blockIdx.x * blockDim.x + threadIdx.x;
    float tcv = (j < TCLEN) ? g_tc[j] : 0.0f;
    float v = fmaxf(0.0f, ca * tcv + cb * bk[j]);
    g_out3[j] = v;
    sh[threadIdx.x] = (double)((double)v * (double)v);
    __syncthreads();
    for (int s = 128; s > 0; s >>= 1) {
        if (threadIdx.x < s) sh[threadIdx.x] += sh[threadIdx.x + s];
        __syncthreads();
    }
    if (threadIdx.x == 0) atomicAdd(&g_acc[12], sh[0]);
}

// logits_raw[r] = trans[r,:] . out3  -- fp32, 8 independent accumulators
__global__ void __launch_bounds__(256) k_matvec(const float* __restrict__ trans) {
    __shared__ float sh[256];
    const int row = blockIdx.x;
    const float4* tr = (const float4*)(trans + (size_t)row * OUTLEN);
    const float4* ov = (const float4*)g_out3;
    float acc[8];
#pragma unroll
    for (int i = 0; i < 8; i++) acc[i] = 0.0f;
    for (int i = threadIdx.x; i < OUTLEN / 8; i += 256) {
        float4 t0 = tr[2 * i], t1 = tr[2 * i + 1];
        float4 o0 = ov[2 * i], o1 = ov[2 * i + 1];
        acc[0] = fmaf(t0.x, o0.x, acc[0]);
        acc[1] = fmaf(t0.y, o0.y, acc[1]);
        acc[2] = fmaf(t0.z, o0.z, acc[2]);
        acc[3] = fmaf(t0.w, o0.w, acc[3]);
        acc[4] = fmaf(t1.x, o1.x, acc[4]);
        acc[5] = fmaf(t1.y, o1.y, acc[5]);
        acc[6] = fmaf(t1.z, o1.z, acc[6]);
        acc[7] = fmaf(t1.w, o1.w, acc[7]);
    }
    float a = ((acc[0] + acc[1]) + (acc[2] + acc[3]))
            + ((acc[4] + acc[5]) + (acc[6] + acc[7]));
    sh[threadIdx.x] = a; __syncthreads();
    for (int s = 128; s > 0; s >>= 1) {
        if (threadIdx.x < s) sh[threadIdx.x] += sh[threadIdx.x + s];
        __syncthreads();
    }
    if (threadIdx.x == 0) g_logits[row] = sh[0];
}

// logmap0 scale, per-row euc_to_hyp (scalar), softmax over 512
__global__ void k_final(float* __restrict__ out) {
    const int t = threadIdx.x;
    const double C  = 1e-5;
    const double SC = sqrt(C);

    double pn = sqrt(g_acc[12]); if (pn < 1e-15) pn = 1e-15;
    double z = SC * pn;
    if (z > 1.0 - 1e-7) z = 1.0 - 1e-7;
    double slog = atanh(z) / (SC * pn);

    double l = slog * (double)g_logits[t];
    double un = fabs(l); if (un < 1e-15) un = 1e-15;
    double scn = SC * un;
    double val = tanh(scn) / scn * l;
    double maxnorm = (1.0 - 4e-3) / SC;
    double av = fabs(val); if (av < 1e-15) av = 1e-15;
    if (av > maxnorm) val = val / av * maxnorm;

    __shared__ double sh[NUM_CLASSES];
    sh[t] = val; __syncthreads();
    for (int s = 256; s > 0; s >>= 1) {
        if (t < s) sh[t] = fmax(sh[t], sh[t + s]);
        __syncthreads();
    }
    double m = sh[0];
    __syncthreads();
    double e = exp(val - m);
    sh[t] = e; __syncthreads();
    for (int s = 256; s > 0; s >>= 1) {
        if (t < s) sh[t] += sh[t + s];
        __syncthreads();
    }
    out[t] = (float)(e / sh[0]);
}

extern "C" void kernel_launch(void* const* d_in, const int* in_sizes, int n_in,
                              void* d_out, int out_size) {
    const float* hk = nullptr;
    const float* w[4]   = {nullptr, nullptr, nullptr, nullptr};
    const float* bkk[4] = {nullptr, nullptr, nullptr, nullptr};
    const float* trans = nullptr;
    int wi = 0;
    for (int i = 0; i < n_in; i++) {
        int s = in_sizes[i];
        const float* p = (const float*)d_in[i];
        if      (s == INPUT_SIZE) hk = p;
        else if (s == FILTER_LEN) { if (wi < 4) w[wi++] = p; }
        else if (s == 40960) bkk[0] = p;
        else if (s == 49152) bkk[1] = p;
        else if (s == 57344) bkk[2] = p;
        else if (s == 65536) bkk[3] = p;
        else if (s == NUM_CLASSES * OUTLEN) trans = p;
    }

    const int convLens[4] = {40960, 49152, 57344, 65536};

    k_init<<<1, 32>>>();
    for (int i = 0; i < 4; i++) {
        const float* bkprev = (i == 0) ? nullptr : bkk[i - 1];
        k_conv<<<dim3(TCLEN / CT_T, CT_KCHUNKS), CT_THREADS>>>(hk, w[i], bkprev, i);
        k_reduce<<<128, 256>>>(bkk[i], convLens[i], i);
    }
    k_elem3<<<OUTLEN / 256, 256>>>(bkk[3]);
    k_matvec<<<NUM_CLASSES, 256>>>(trans);
    k_final<<<1, NUM_CLASSES>>>((float*)d_out);
}

// round 4
// speedup vs baseline: 2.2061x; 1.0558x over previous
#include <cuda_runtime.h>
#include <math.h>

#define INPUT_SIZE 32768
#define FILTER_LEN 8192
#define NUM_CLASSES 512
#define TCLEN 40960      // conv full-length rounded (40959 real outputs, [40959]=0)
#define OUTLEN 65536

// Conv tiling: block computes CT_T outputs as two interleaved halves of CT_HALF.
#define CT_T 2048
#define CT_HALF 1024
#define CT_KC 512        // filter-chunk per block
#define CT_KCHUNKS 16    // 8192 / 512
#define CT_THREADS 128   // each thread: 8 low + 8 high outputs

#define SXP_PHYS 1736    // phys(1543)+1, phys(i)=i+(i>>3)

typedef unsigned long long u64;

static __device__ __align__(16) float g_part[CT_KCHUNKS * TCLEN]; // split-K partials
static __device__ __align__(16) float g_tc[TCLEN];                // current layer conv output
static __device__ __align__(16) float g_out3[OUTLEN];             // final layer full vector
static __device__ float  g_logits[NUM_CLASSES];
static __device__ double g_acc[16];      // [3i..3i+2]=Stt,Stb,Sbb ; [12]=||out3||^2
static __device__ float  g_ca[4], g_cb[4];
static __device__ unsigned g_ctr[8];     // completion tickets

// ---- packed f32x2 helpers (Blackwell) ----
static __device__ __forceinline__ u64 pk2(float lo, float hi) {
    u64 r;
    asm("mov.b64 %0, {%1, %2};" : "=l"(r) : "f"(lo), "f"(hi));
    return r;
}
static __device__ __forceinline__ void fma2(u64& d, u64 a, u64 b) {
    asm("fma.rn.f32x2 %0, %1, %2, %0;" : "+l"(d) : "l"(a), "l"(b));
}
static __device__ __forceinline__ void unpk2(u64 v, float& lo, float& hi) {
    asm("mov.b64 {%0, %1}, %2;" : "=f"(lo), "=f"(hi) : "l"(v));
}

__global__ void k_init() {
    int t = threadIdx.x;
    if (t < 16) g_acc[t] = 0.0;
    if (t < 8)  g_ctr[t] = 0u;
}

// tc[j] = sum_k w[k] * x[j-k]; x for layer>0 generated inline:
// x[gi] = relu(ca*g_tc[gi] + cb*bkprev[gi])
// Two-half interleave: f32x2 lanes = (output j, output j+1024).
__global__ void __launch_bounds__(CT_THREADS) k_conv(const float* __restrict__ xin,
                                                     const float* __restrict__ w,
                                                     const float* __restrict__ bkprev,
                                                     int layer) {
    __shared__ u64 wpk[CT_KC];       // reversed filter chunk, packed (w,w)
    __shared__ u64 sxp[SXP_PHYS];    // swizzled packed x: (.lo=x_low, .hi=x_high)

    const int tid    = threadIdx.x;
    const int jBase  = blockIdx.x * CT_T;
    const int k0     = blockIdx.y * CT_KC;
    const int lowIdx = jBase - k0 - (CT_KC - 1);

    for (int t = tid; t < CT_KC; t += CT_THREADS) {
        float wv = w[k0 + t];
        wpk[CT_KC - 1 - t] = pk2(wv, wv);   // reversed so x-window ascends with tap index
    }

    if (layer == 0) {
        for (int i = tid; i < CT_HALF + CT_KC; i += CT_THREADS) {
            int g0 = lowIdx + i;
            int g1 = g0 + CT_HALF;
            float a = (g0 >= 0 && g0 < INPUT_SIZE) ? xin[g0] : 0.0f;
            float b = (g1 >= 0 && g1 < INPUT_SIZE) ? xin[g1] : 0.0f;
            sxp[i + (i >> 3)] = pk2(a, b);
        }
    } else {
        const float ca = g_ca[layer - 1], cb = g_cb[layer - 1];
        for (int i = tid; i < CT_HALF + CT_KC; i += CT_THREADS) {
            int g0 = lowIdx + i;
            int g1 = g0 + CT_HALF;
            float a = 0.0f, b = 0.0f;
            if (g0 >= 0 && g0 < INPUT_SIZE)
                a = fmaxf(0.0f, ca * g_tc[g0] + cb * bkprev[g0]);
            if (g1 >= 0 && g1 < INPUT_SIZE)
                b = fmaxf(0.0f, ca * g_tc[g1] + cb * bkprev[g1]);
            sxp[i + (i >> 3)] = pk2(a, b);
        }
    }
    __syncthreads();

    u64 pacc[8];
#pragma unroll
    for (int r = 0; r < 8; r++) pacc[r] = pk2(0.0f, 0.0f);

    const int tb = tid * 8;

    // circular 16-slot window: slot s <-> logical tb + kb + s (phase A entry)
    u64 xw[16];
    {
        int pb = tb + (tb >> 3);
#pragma unroll
        for (int s = 0; s < 8; s++)  xw[s] = sxp[pb + s];
#pragma unroll
        for (int s = 8; s < 16; s++) xw[s] = sxp[pb + 1 + s];
    }

    for (int kb = 0; kb < CT_KC; kb += 16) {
        // phase A: taps kb..kb+7, operand slot = u + r (<=14)
#pragma unroll
        for (int u = 0; u < 8; u++) {
            u64 wq = wpk[kb + u];
#pragma unroll
            for (int r = 0; r < 8; r++) fma2(pacc[r], wq, xw[u + r]);
        }
        // refill slots 0..7 with logical tb+kb+16..+23
        {
            int base = tb + kb + 16;
            int pb = base + (base >> 3);
#pragma unroll
            for (int s = 0; s < 8; s++) xw[s] = sxp[pb + s];
        }
        // phase B: taps kb+8..kb+15, operand slot = (u + r + 8) & 15
#pragma unroll
        for (int u = 0; u < 8; u++) {
            u64 wq = wpk[kb + 8 + u];
#pragma unroll
            for (int r = 0; r < 8; r++) fma2(pacc[r], wq, xw[(u + r + 8) & 15]);
        }
        // refill slots 8..15 with logical tb+kb+24..+31 (last iter reads pad, unused)
        {
            int base = tb + kb + 24;
            int pb = base + (base >> 3);
#pragma unroll
            for (int s = 0; s < 8; s++) xw[8 + s] = sxp[pb + s];
        }
    }

    float lo[8], hi[8];
#pragma unroll
    for (int r = 0; r < 8; r++) unpk2(pacc[r], lo[r], hi[r]);

    float* basep = &g_part[blockIdx.y * TCLEN + jBase + tb];
    ((float4*)basep)[0] = make_float4(lo[0], lo[1], lo[2], lo[3]);
    ((float4*)basep)[1] = make_float4(lo[4], lo[5], lo[6], lo[7]);
    float* basph = basep + CT_HALF;
    ((float4*)basph)[0] = make_float4(hi[0], hi[1], hi[2], hi[3]);
    ((float4*)basph)[1] = make_float4(hi[4], hi[5], hi[6], hi[7]);
}

// scalar coefficients: out = relu(ca*tc + cb*bk)
static __device__ __forceinline__ void compute_coeffs(int slot, float* pca, float* pcb) {
    const double C  = 1e-5;
    const double SC = sqrt(C);
    double Stt = g_acc[slot * 3 + 0];
    double Stb = g_acc[slot * 3 + 1];
    double Sbb = g_acc[slot * 3 + 2];

    double un = sqrt(Stt); if (un < 1e-15) un = 1e-15;
    double scn = SC * un;
    double gexp = tanh(scn) / scn;            // expmap0 scale
    double nafter = gexp * un;
    double maxnorm = (1.0 - 4e-3) / SC;
    double g = (nafter > maxnorm) ? (maxnorm / un) : gexp;  // proj

    double x2 = g * g * Stt;
    double xy = g * Stb;
    double y2 = Sbb;
    double A  = 1.0 + 2.0 * C * xy + C * y2;
    double B  = 1.0 - C * x2;
    double den = 1.0 + 2.0 * C * xy + C * C * x2 * y2;
    if (den < 1e-15) den = 1e-15;
    *pca = (float)(A * g / den);
    *pcb = (float)(B / den);
}

// combine split-K partials -> g_tc ; accumulate Stt, Stb, Sbb; last block computes coeffs
// grid = 40 blocks x 256 thr; one float4 of tc per thread.
__global__ void __launch_bounds__(256) k_reduce(const float* __restrict__ bk,
                                                int convLen, int slot) {
    __shared__ double sh[256];
    const int t = threadIdx.x;
    const int idx = blockIdx.x * 256 + t;   // float4 index
    float stt = 0.0f, stb = 0.0f, sbb = 0.0f;

    {
        const float4* gp = (const float4*)g_part;
        float4 s = gp[idx];
#pragma unroll
        for (int c = 1; c < CT_KCHUNKS; c++) {
            float4 v = gp[c * (TCLEN / 4) + idx];
            s.x += v.x; s.y += v.y; s.z += v.z; s.w += v.w;
        }
        ((float4*)g_tc)[idx] = s;
        float4 b = ((const float4*)bk)[idx];
        stt = fmaf(s.x, s.x, fmaf(s.y, s.y, fmaf(s.z, s.z, s.w * s.w)));
        stb = fmaf(s.x, b.x, fmaf(s.y, b.y, fmaf(s.z, b.z, s.w * b.w)));
    }
    for (int i = idx; i < convLen / 4; i += 40 * 256) {
        float4 b = ((const float4*)bk)[i];
        sbb = fmaf(b.x, b.x, fmaf(b.y, b.y, fmaf(b.z, b.z, fmaf(b.w, b.w, sbb))));
    }

    sh[t] = (double)stt; __syncthreads();
    for (int s = 128; s > 0; s >>= 1) { if (t < s) sh[t] += sh[t + s]; __syncthreads(); }
    if (t == 0) atomicAdd(&g_acc[slot * 3 + 0], sh[0]);
    __syncthreads();
    sh[t] = (double)stb; __syncthreads();
    for (int s = 128; s > 0; s >>= 1) { if (t < s) sh[t] += sh[t + s]; __syncthreads(); }
    if (t == 0) atomicAdd(&g_acc[slot * 3 + 1], sh[0]);
    __syncthreads();
    sh[t] = (double)sbb; __syncthreads();
    for (int s = 128; s > 0; s >>= 1) { if (t < s) sh[t] += sh[t + s]; __syncthreads(); }
    if (t == 0) {
        atomicAdd(&g_acc[slot * 3 + 2], sh[0]);
        __threadfence();
        if (atomicAdd(&g_ctr[slot], 1u) == gridDim.x - 1) {
            __threadfence();
            float ca, cb;
            compute_coeffs(slot, &ca, &cb);
            g_ca[slot] = ca;
            g_cb[slot] = cb;
        }
    }
}

// layer 3: full 65536 output + ||out3||^2. grid 64x256, one float4/thread.
__global__ void __launch_bounds__(256) k_elem3(const float* __restrict__ bk) {
    __shared__ double sh[256];
    const float ca = g_ca[3], cb = g_cb[3];
    const int idx = blockIdx.x * 256 + threadIdx.x;  // float4 index, < 16384
    float4 tc = make_float4(0.f, 0.f, 0.f, 0.f);
    if (idx < TCLEN / 4) tc = ((const float4*)g_tc)[idx];
    float4 b = ((const float4*)bk)[idx];
    float4 v;
    v.x = fmaxf(0.0f, ca * tc.x + cb * b.x);
    v.y = fmaxf(0.0f, ca * tc.y + cb * b.y);
    v.z = fmaxf(0.0f, ca * tc.z + cb * b.z);
    v.w = fmaxf(0.0f, ca * tc.w + cb * b.w);
    ((float4*)g_out3)[idx] = v;
    double n = (double)v.x * v.x + (double)v.y * v.y
             + (double)v.z * v.z + (double)v.w * v.w;
    sh[threadIdx.x] = n; __syncthreads();
    for (int s = 128; s > 0; s >>= 1) {
        if (threadIdx.x < s) sh[threadIdx.x] += sh[threadIdx.x + s];
        __syncthreads();
    }
    if (threadIdx.x == 0) atomicAdd(&g_acc[12], sh[0]);
}

// logits_raw[r] = trans[r,:] . out3 ; last block (ticket) runs the softmax.
__global__ void __launch_bounds__(256) k_matvec(const float* __restrict__ trans,
                                                float* __restrict__ out) {
    __shared__ float sh[256];
    const int t = threadIdx.x;
    const int row = blockIdx.x;
    const float4* tr = (const float4*)(trans + (size_t)row * OUTLEN);
    const float4* ov = (const float4*)g_out3;
    float acc[8];
#pragma unroll
    for (int i = 0; i < 8; i++) acc[i] = 0.0f;
    for (int i = t; i < OUTLEN / 8; i += 256) {
        float4 t0 = tr[2 * i], t1 = tr[2 * i + 1];
        float4 o0 = ov[2 * i], o1 = ov[2 * i + 1];
        acc[0] = fmaf(t0.x, o0.x, acc[0]);
        acc[1] = fmaf(t0.y, o0.y, acc[1]);
        acc[2] = fmaf(t0.z, o0.z, acc[2]);
        acc[3] = fmaf(t0.w, o0.w, acc[3]);
        acc[4] = fmaf(t1.x, o1.x, acc[4]);
        acc[5] = fmaf(t1.y, o1.y, acc[5]);
        acc[6] = fmaf(t1.z, o1.z, acc[6]);
        acc[7] = fmaf(t1.w, o1.w, acc[7]);
    }
    float a = ((acc[0] + acc[1]) + (acc[2] + acc[3]))
            + ((acc[4] + acc[5]) + (acc[6] + acc[7]));
    sh[t] = a; __syncthreads();
    for (int s = 128; s > 0; s >>= 1) {
        if (t < s) sh[t] += sh[t + s];
        __syncthreads();
    }
    __shared__ int s_last;
    if (t == 0) {
        g_logits[row] = sh[0];
        __threadfence();
        s_last = (atomicAdd(&g_ctr[4], 1u) == gridDim.x - 1) ? 1 : 0;
    }
    __syncthreads();
    if (!s_last) return;
    __threadfence();

    // ---- fused final: logmap0 scale, euc_to_hyp per row, softmax over 512 ----
    const double C  = 1e-5;
    const double SC = sqrt(C);
    double pn = sqrt(g_acc[12]); if (pn < 1e-15) pn = 1e-15;
    double z = SC * pn;
    if (z > 1.0 - 1e-7) z = 1.0 - 1e-7;
    double slog = atanh(z) / (SC * pn);
    double maxnorm = (1.0 - 4e-3) / SC;

    double val[2];
#pragma unroll
    for (int q = 0; q < 2; q++) {
        int r = t + 256 * q;
        double l = slog * (double)g_logits[r];
        double un = fabs(l); if (un < 1e-15) un = 1e-15;
        double scn = SC * un;
        double v = tanh(scn) / scn * l;
        double av = fabs(v); if (av < 1e-15) av = 1e-15;
        if (av > maxnorm) v = v / av * maxnorm;
        val[q] = v;
    }
    __shared__ double sd[256];
    sd[t] = fmax(val[0], val[1]); __syncthreads();
    for (int s = 128; s > 0; s >>= 1) {
        if (t < s) sd[t] = fmax(sd[t], sd[t + s]);
        __syncthreads();
    }
    double m = sd[0];
    __syncthreads();
    double e0 = exp(val[0] - m), e1 = exp(val[1] - m);
    sd[t] = e0 + e1; __syncthreads();
    for (int s = 128; s > 0; s >>= 1) {
        if (t < s) sd[t] += sd[t + s];
        __syncthreads();
    }
    double inv = 1.0 / sd[0];
    out[t]       = (float)(e0 * inv);
    out[t + 256] = (float)(e1 * inv);
}

extern "C" void kernel_launch(void* const* d_in, const int* in_sizes, int n_in,
                              void* d_out, int out_size) {
    const float* hk = nullptr;
    const float* w[4]   = {nullptr, nullptr, nullptr, nullptr};
    const float* bkk[4] = {nullptr, nullptr, nullptr, nullptr};
    const float* trans = nullptr;
    int wi = 0;
    for (int i = 0; i < n_in; i++) {
        int s = in_sizes[i];
        const float* p = (const float*)d_in[i];
        if      (s == INPUT_SIZE) hk = p;
        else if (s == FILTER_LEN) { if (wi < 4) w[wi++] = p; }
        else if (s == 40960) bkk[0] = p;
        else if (s == 49152) bkk[1] = p;
        else if (s == 57344) bkk[2] = p;
        else if (s == 65536) bkk[3] = p;
        else if (s == NUM_CLASSES * OUTLEN) trans = p;
    }

    const int convLens[4] = {40960, 49152, 57344, 65536};

    k_init<<<1, 32>>>();
    for (int i = 0; i < 4; i++) {
        const float* bkprev = (i == 0) ? nullptr : bkk[i - 1];
        k_conv<<<dim3(TCLEN / CT_T, CT_KCHUNKS), CT_THREADS>>>(hk, w[i], bkprev, i);
        k_reduce<<<40, 256>>>(bkk[i], convLens[i], i);
    }
    k_elem3<<<OUTLEN / 1024, 256>>>(bkk[3]);
    k_matvec<<<NUM_CLASSES, 256>>>(trans, (float*)d_out);
}